// round 6
// baseline (speedup 1.0000x reference)
#include <cuda_runtime.h>
#include <math_constants.h>
#include <cstdint>

// VectorQuantizer: emulated-fp32 GEMM via 3xTF32 mma.sync (sm_80+ PTX).
// latents [65536,64] f32, embedding [512,64] f32.
// out[0] = vq_loss, out[1..] = quantized_st (only 4B-aligned -> scalar stores).
//
// Numerics contract (R1/R2 scored rel_err 0.0; R5 showed ONE argmin flip fails):
//   dist = fl(fl(a + b) - 2c), a=||x||^2, b=||e||^2 sequential fp32 chains,
//   argmin first-index ties. The fl(a+b) at scale ~64 (ulp 7.6e-6) absorbs
//   c-perturbations ~1e-9. 3xTF32 split (hi+lo) reproduces c to ~2e-9 of the
//   fp32 chain -- same magnitude as XLA-vs-sequential reorder, which gave 0 flips.

#define NROWS 65536
#define KEMB 512
#define DDIM 64
#define TILE_M 128
#define NCTAS (NROWS / TILE_M)   // 512
#define NTHREADS 128             // 4 warps; warp owns 32 rows (2 m16 tiles)
#define CHUNK 128
#define NCHUNKS (KEMB / CHUNK)   // 4
#define KT 8                     // 8 k-tiles of k8 -> K=64
#define XSTR 80                  // Xs row stride (words)

// smem layout (bytes). Xs (40960B) is a union inside EsP (65536B).
#define SM_ESP   0
#define SM_AS    65536           // float[128]
#define SM_BN    66048           // float[512]
#define SM_IDX   68096           // int[128]
#define SM_WSUM  68608           // double[4]
#define SM_TOTAL 68640

__device__ double g_part[NCTAS];

__device__ __forceinline__ uint32_t f2tf32(float f) {
    uint32_t r;
    asm("cvt.rna.tf32.f32 %0, %1;" : "=r"(r) : "f"(f));
    return r;
}
__device__ __forceinline__ void split_tf32(float x, uint32_t& hi, uint32_t& lo) {
    hi = f2tf32(x);
    lo = f2tf32(__fsub_rn(x, __uint_as_float(hi)));
}
__device__ __forceinline__ void mma_tf32(float* d, const uint32_t* a,
                                         uint32_t b0, uint32_t b1) {
    asm volatile(
        "mma.sync.aligned.m16n8k8.row.col.f32.tf32.tf32.f32 "
        "{%0,%1,%2,%3}, {%4,%5,%6,%7}, {%8,%9}, {%0,%1,%2,%3};"
        : "+f"(d[0]), "+f"(d[1]), "+f"(d[2]), "+f"(d[3])
        : "r"(a[0]), "r"(a[1]), "r"(a[2]), "r"(a[3]), "r"(b0), "r"(b1));
}

__global__ __launch_bounds__(NTHREADS, 2)
void vq_mma_kernel(const float* __restrict__ lat,
                   const float* __restrict__ emb,
                   float* __restrict__ quant /* d_out + 1, 4B-aligned only */)
{
    extern __shared__ char smem[];
    uint32_t* Xs  = (uint32_t*)(smem + SM_ESP);   // staging union
    char*     EsP = smem + SM_ESP;                // packed E cells
    float*    As  = (float*)(smem + SM_AS);
    float*    Bn  = (float*)(smem + SM_BN);
    int*      IdxS = (int*)(smem + SM_IDX);
    double*   Wsum = (double*)(smem + SM_WSUM);

    const int tid  = threadIdx.x;
    const int w    = tid >> 5;
    const int lane = tid & 31;
    const int qid  = lane >> 2;   // 0..7
    const int qsub = lane & 3;    // 0..3
    const int rowBase = blockIdx.x * TILE_M;

    // ---- stage raw X tile into Xs (stride 80 words) ----
    {
        const float4* X4 = (const float4*)(lat + (size_t)rowBase * DDIM);
        #pragma unroll
        for (int p = 0; p < 16; p++) {
            int i = p * NTHREADS + tid;
            int r = i >> 4, v = i & 15;
            *(float4*)&Xs[r * XSTR + v * 4] = X4[i];
        }
    }
    // ---- b = ||e||^2: sequential fp32 chain (matches R1; rel_err 0.0) ----
    #pragma unroll
    for (int c = 0; c < 4; c++) {
        int n = c * NTHREADS + tid;
        const float* e = emb + (size_t)n * DDIM;
        float s = 0.f;
        #pragma unroll
        for (int d = 0; d < DDIM; d++)
            s = __fadd_rn(s, __fmul_rn(e[d], e[d]));
        Bn[n] = s;
    }
    __syncthreads();

    // ---- a = ||x||^2: sequential fp32 chain ----
    {
        float s = 0.f;
        #pragma unroll
        for (int d = 0; d < DDIM; d++) {
            float v = __uint_as_float(Xs[tid * XSTR + d]);
            s = __fadd_rn(s, __fmul_rn(v, v));
        }
        As[tid] = s;
    }
    __syncthreads();

    // ---- load A fragments and split hi/lo (resident: 128 regs) ----
    uint32_t Ahi[2][KT][4], Alo[2][KT][4];
    #pragma unroll
    for (int m = 0; m < 2; m++) {
        const int r = w * 32 + m * 16 + qid;
        #pragma unroll
        for (int kt = 0; kt < KT; kt++) {
            const int k = kt * 8 + qsub;
            float x0 = __uint_as_float(Xs[r * XSTR + k]);
            float x1 = __uint_as_float(Xs[(r + 8) * XSTR + k]);
            float x2 = __uint_as_float(Xs[r * XSTR + k + 4]);
            float x3 = __uint_as_float(Xs[(r + 8) * XSTR + k + 4]);
            split_tf32(x0, Ahi[m][kt][0], Alo[m][kt][0]);
            split_tf32(x1, Ahi[m][kt][1], Alo[m][kt][1]);
            split_tf32(x2, Ahi[m][kt][2], Alo[m][kt][2]);
            split_tf32(x3, Ahi[m][kt][3], Alo[m][kt][3]);
        }
    }
    float a[4];
    #pragma unroll
    for (int j = 0; j < 4; j++)           // j = m*2 + half
        a[j] = As[w * 32 + (j >> 1) * 16 + (j & 1) * 8 + qid];
    __syncthreads();   // Xs dead; EsP may be written

    float bestD[4];
    int   bestI[4];
    #pragma unroll
    for (int j = 0; j < 4; j++) { bestD[j] = CUDART_INF_F; bestI[j] = 0; }

    const int n_off = lane >> 2;   // 0..7 for staging

    for (int ch = 0; ch < NCHUNKS; ch++) {
        // ---- stage packed E cells: EsP[kt][n][qsub] = {hi_k, hi_k4, lo_k, lo_k4}
        // Store pattern: per iter, warp covers 8 consecutive n x 4 qsub at one kt
        // (word offsets 16*((n)&1)+4*qsub per 8-lane phase -> conflict-free).
        #pragma unroll 4
        for (int it = 0; it < 32; it++) {
            int idx = it * 4 + w;                 // 0..127
            int kt = idx >> 4;
            int n  = ((idx & 15) << 3) + n_off;   // 0..127
            int k  = kt * 8 + qsub;
            const float* ep = emb + ((size_t)(ch * CHUNK + n)) * DDIM + k;
            uint32_t h0, l0, h1, l1;
            split_tf32(__ldg(ep),     h0, l0);
            split_tf32(__ldg(ep + 4), h1, l1);
            *(uint4*)(EsP + kt * 8192 + n * 64 + qsub * 16) =
                make_uint4(h0, h1, l0, l1);
        }
        __syncthreads();

        // ---- 16 n-tiles of 8 codes ----
        for (int nt = 0; nt < 16; nt++) {
            // B cells for all kt: one LDS.128 each (conflict-free)
            uint4 B[KT];
            const char* bp = EsP + (nt * 8 + qid) * 64 + qsub * 16;
            #pragma unroll
            for (int kt = 0; kt < KT; kt++)
                B[kt] = *(const uint4*)(bp + kt * 8192);

            float acc[2][4];
            #pragma unroll
            for (int m = 0; m < 2; m++) {
                #pragma unroll
                for (int q = 0; q < 4; q++) acc[m][q] = 0.f;
                #pragma unroll
                for (int kt = 0; kt < KT; kt++)   // small terms first
                    mma_tf32(acc[m], Ahi[m][kt], B[kt].z, B[kt].w);  // hi*lo
                #pragma unroll
                for (int kt = 0; kt < KT; kt++)
                    mma_tf32(acc[m], Alo[m][kt], B[kt].x, B[kt].y);  // lo*hi
                #pragma unroll
                for (int kt = 0; kt < KT; kt++)
                    mma_tf32(acc[m], Ahi[m][kt], B[kt].x, B[kt].y);  // hi*hi
            }

            // dist = fl(fl(a+b) - 2c); strict < keeps first index
            const int col0 = ch * CHUNK + nt * 8 + qsub * 2;
            const float b0 = Bn[col0], b1 = Bn[col0 + 1];
            #pragma unroll
            for (int j = 0; j < 4; j++) {
                float c0 = acc[j >> 1][(j & 1) * 2];
                float c1 = acc[j >> 1][(j & 1) * 2 + 1];
                float d0 = __fsub_rn(__fadd_rn(a[j], b0), 2.0f * c0);
                float d1 = __fsub_rn(__fadd_rn(a[j], b1), 2.0f * c1);
                if (d0 < bestD[j]) { bestD[j] = d0; bestI[j] = col0; }
                if (d1 < bestD[j]) { bestD[j] = d1; bestI[j] = col0 + 1; }
            }
        }
        __syncthreads();   // before EsP restaged
    }

    // ---- quad reduce (qsub lanes share rows), first-index tie-break ----
    #pragma unroll
    for (int j = 0; j < 4; j++) {
        float d = bestD[j];
        int   idx = bestI[j];
        #pragma unroll
        for (int off = 1; off <= 2; off <<= 1) {
            float od = __shfl_xor_sync(0xffffffffu, d, off);
            int   oi = __shfl_xor_sync(0xffffffffu, idx, off);
            if (od < d || (od == d && oi < idx)) { d = od; idx = oi; }
        }
        if (qsub == 0)
            IdxS[w * 32 + (j >> 1) * 16 + (j & 1) * 8 + qid] = idx;
    }
    __syncthreads();

    // ---- gather + straight-through write (scalar stores) + fp64 loss ----
    double ls = 0.0;
    {
        const int seg  = tid & 15;
        const int rsub = tid >> 4;
        #pragma unroll
        for (int p = 0; p < 16; p++) {
            int row = p * 8 + rsub;
            int idx = IdxS[row];
            float4 q = __ldg((const float4*)(emb + (size_t)idx * DDIM + seg * 4));
            float4 l = __ldg((const float4*)(lat + (size_t)(rowBase + row) * DDIM + seg * 4));
            float t0 = q.x - l.x, t1 = q.y - l.y, t2 = q.z - l.z, t3 = q.w - l.w;
            ls += (double)t0 * t0 + (double)t1 * t1
                + (double)t2 * t2 + (double)t3 * t3;
            float* o = quant + (size_t)(rowBase + row) * DDIM + seg * 4;
            o[0] = l.x + t0;
            o[1] = l.y + t1;
            o[2] = l.z + t2;
            o[3] = l.w + t3;
        }
    }

    #pragma unroll
    for (int off = 16; off >= 1; off >>= 1)
        ls += __shfl_xor_sync(0xffffffffu, ls, off);
    if (lane == 0) Wsum[w] = ls;
    __syncthreads();
    if (tid == 0)
        g_part[blockIdx.x] = Wsum[0] + Wsum[1] + Wsum[2] + Wsum[3];
}

// ---------------- finalize vq_loss ----------------
__global__ void vq_finalize_kernel(float* __restrict__ out) {
    __shared__ double sm2[NCTAS];
    int t = threadIdx.x;
    sm2[t] = g_part[t];
    __syncthreads();
    for (int s = NCTAS / 2; s >= 1; s >>= 1) {
        if (t < s) sm2[t] += sm2[t + s];
        __syncthreads();
    }
    if (t == 0) {
        double m = sm2[0] / (double)((size_t)NROWS * DDIM);
        out[0] = (float)(1.25 * m);
    }
}

extern "C" void kernel_launch(void* const* d_in, const int* in_sizes, int n_in,
                              void* d_out, int out_size) {
    const float* lat = (const float*)d_in[0];   // latents  [65536, 64]
    const float* emb = (const float*)d_in[1];   // embedding [512, 64]
    float* out = (float*)d_out;

    cudaFuncSetAttribute(vq_mma_kernel, cudaFuncAttributeMaxDynamicSharedMemorySize, SM_TOTAL);
    vq_mma_kernel<<<NCTAS, NTHREADS, SM_TOTAL>>>(lat, emb, out + 1);
    vq_finalize_kernel<<<1, NCTAS>>>(out);
}

// round 7
// speedup vs baseline: 1.0124x; 1.0124x over previous
#include <cuda_runtime.h>
#include <math_constants.h>
#include <cstdint>

// VectorQuantizer: emulated-fp32 GEMM via 3xTF32 mma.sync (sm_80+ PTX).
// latents [65536,64] f32, embedding [512,64] f32.
// out[0] = vq_loss, out[1..] = quantized_st (only 4B-aligned -> scalar stores).
//
// Numerics contract (R6 scored rel_err 0.0): dist = fl(fl(a+b) - 2c),
// a,b sequential fp32 chains, c via 3xTF32 split; c-perturbations ~1e-9
// are absorbed by the fl(a+b) grid at scale ~64.
// R7 change: 3 independent accumulator chains per m-tile (6 per warp) to
// break the 24-deep MMA RAW chain that made R6 latency-bound (28 cyc/MMA).

#define NROWS 65536
#define KEMB 512
#define DDIM 64
#define TILE_M 128
#define NCTAS (NROWS / TILE_M)   // 512
#define NTHREADS 128             // 4 warps; warp owns 32 rows (2 m16 tiles)
#define CHUNK 128
#define NCHUNKS (KEMB / CHUNK)   // 4
#define KT 8                     // 8 k-tiles of k8 -> K=64
#define XSTR 80                  // Xs row stride (words)

// smem layout (bytes). Xs (40960B) is a union inside EsP (65536B).
#define SM_ESP   0
#define SM_AS    65536           // float[128]
#define SM_BN    66048           // float[512]
#define SM_IDX   68096           // int[128]
#define SM_WSUM  68608           // double[4]
#define SM_TOTAL 68640

__device__ double g_part[NCTAS];

__device__ __forceinline__ uint32_t f2tf32(float f) {
    uint32_t r;
    asm("cvt.rna.tf32.f32 %0, %1;" : "=r"(r) : "f"(f));
    return r;
}
__device__ __forceinline__ void split_tf32(float x, uint32_t& hi, uint32_t& lo) {
    hi = f2tf32(x);
    lo = f2tf32(__fsub_rn(x, __uint_as_float(hi)));
}
__device__ __forceinline__ void mma_tf32(float* d, const uint32_t* a,
                                         uint32_t b0, uint32_t b1) {
    asm volatile(
        "mma.sync.aligned.m16n8k8.row.col.f32.tf32.tf32.f32 "
        "{%0,%1,%2,%3}, {%4,%5,%6,%7}, {%8,%9}, {%0,%1,%2,%3};"
        : "+f"(d[0]), "+f"(d[1]), "+f"(d[2]), "+f"(d[3])
        : "r"(a[0]), "r"(a[1]), "r"(a[2]), "r"(a[3]), "r"(b0), "r"(b1));
}

__global__ __launch_bounds__(NTHREADS, 2)
void vq_mma_kernel(const float* __restrict__ lat,
                   const float* __restrict__ emb,
                   float* __restrict__ quant /* d_out + 1, 4B-aligned only */)
{
    extern __shared__ char smem[];
    uint32_t* Xs  = (uint32_t*)(smem + SM_ESP);   // staging union
    char*     EsP = smem + SM_ESP;                // packed E cells
    float*    As  = (float*)(smem + SM_AS);
    float*    Bn  = (float*)(smem + SM_BN);
    int*      IdxS = (int*)(smem + SM_IDX);
    double*   Wsum = (double*)(smem + SM_WSUM);

    const int tid  = threadIdx.x;
    const int w    = tid >> 5;
    const int lane = tid & 31;
    const int qid  = lane >> 2;   // 0..7
    const int qsub = lane & 3;    // 0..3
    const int rowBase = blockIdx.x * TILE_M;

    // ---- stage raw X tile into Xs (stride 80 words) ----
    {
        const float4* X4 = (const float4*)(lat + (size_t)rowBase * DDIM);
        #pragma unroll
        for (int p = 0; p < 16; p++) {
            int i = p * NTHREADS + tid;
            int r = i >> 4, v = i & 15;
            *(float4*)&Xs[r * XSTR + v * 4] = X4[i];
        }
    }
    // ---- b = ||e||^2: sequential fp32 chain ----
    #pragma unroll
    for (int c = 0; c < 4; c++) {
        int n = c * NTHREADS + tid;
        const float* e = emb + (size_t)n * DDIM;
        float s = 0.f;
        #pragma unroll
        for (int d = 0; d < DDIM; d++)
            s = __fadd_rn(s, __fmul_rn(e[d], e[d]));
        Bn[n] = s;
    }
    __syncthreads();

    // ---- a = ||x||^2: sequential fp32 chain ----
    {
        float s = 0.f;
        #pragma unroll
        for (int d = 0; d < DDIM; d++) {
            float v = __uint_as_float(Xs[tid * XSTR + d]);
            s = __fadd_rn(s, __fmul_rn(v, v));
        }
        As[tid] = s;
    }
    __syncthreads();

    // ---- load A fragments and split hi/lo (resident: 128 regs) ----
    uint32_t Ahi[2][KT][4], Alo[2][KT][4];
    #pragma unroll
    for (int m = 0; m < 2; m++) {
        const int r = w * 32 + m * 16 + qid;
        #pragma unroll
        for (int kt = 0; kt < KT; kt++) {
            const int k = kt * 8 + qsub;
            float x0 = __uint_as_float(Xs[r * XSTR + k]);
            float x1 = __uint_as_float(Xs[(r + 8) * XSTR + k]);
            float x2 = __uint_as_float(Xs[r * XSTR + k + 4]);
            float x3 = __uint_as_float(Xs[(r + 8) * XSTR + k + 4]);
            split_tf32(x0, Ahi[m][kt][0], Alo[m][kt][0]);
            split_tf32(x1, Ahi[m][kt][1], Alo[m][kt][1]);
            split_tf32(x2, Ahi[m][kt][2], Alo[m][kt][2]);
            split_tf32(x3, Ahi[m][kt][3], Alo[m][kt][3]);
        }
    }
    float a[4];
    #pragma unroll
    for (int j = 0; j < 4; j++)           // j = m*2 + half
        a[j] = As[w * 32 + (j >> 1) * 16 + (j & 1) * 8 + qid];
    __syncthreads();   // Xs dead; EsP may be written

    float bestD[4];
    int   bestI[4];
    #pragma unroll
    for (int j = 0; j < 4; j++) { bestD[j] = CUDART_INF_F; bestI[j] = 0; }

    const int n_off = lane >> 2;   // 0..7 for staging

    for (int ch = 0; ch < NCHUNKS; ch++) {
        // ---- stage packed E cells: EsP[kt][n][qsub] = {hi_k, hi_k4, lo_k, lo_k4}
        #pragma unroll 4
        for (int it = 0; it < 32; it++) {
            int idx = it * 4 + w;                 // 0..127
            int kt = idx >> 4;
            int n  = ((idx & 15) << 3) + n_off;   // 0..127
            int k  = kt * 8 + qsub;
            const float* ep = emb + ((size_t)(ch * CHUNK + n)) * DDIM + k;
            uint32_t h0, l0, h1, l1;
            split_tf32(__ldg(ep),     h0, l0);
            split_tf32(__ldg(ep + 4), h1, l1);
            *(uint4*)(EsP + kt * 8192 + n * 64 + qsub * 16) =
                make_uint4(h0, h1, l0, l1);
        }
        __syncthreads();

        // ---- 16 n-tiles of 8 codes ----
        for (int nt = 0; nt < 16; nt++) {
            // B cells for all kt: one LDS.128 each (conflict-free)
            uint4 B[KT];
            const char* bp = EsP + (nt * 8 + qid) * 64 + qsub * 16;
            #pragma unroll
            for (int kt = 0; kt < KT; kt++)
                B[kt] = *(const uint4*)(bp + kt * 8192);

            // 6 independent accumulator chains: [m][pass]
            float s1[2][4], s2[2][4], s3[2][4];
            #pragma unroll
            for (int m = 0; m < 2; m++)
                #pragma unroll
                for (int q = 0; q < 4; q++) {
                    s1[m][q] = 0.f; s2[m][q] = 0.f; s3[m][q] = 0.f;
                }

            #pragma unroll
            for (int kt = 0; kt < KT; kt++) {
                mma_tf32(s1[0], Ahi[0][kt], B[kt].z, B[kt].w);  // hi*lo
                mma_tf32(s1[1], Ahi[1][kt], B[kt].z, B[kt].w);
                mma_tf32(s2[0], Alo[0][kt], B[kt].x, B[kt].y);  // lo*hi
                mma_tf32(s2[1], Alo[1][kt], B[kt].x, B[kt].y);
                mma_tf32(s3[0], Ahi[0][kt], B[kt].x, B[kt].y);  // hi*hi
                mma_tf32(s3[1], Ahi[1][kt], B[kt].x, B[kt].y);
            }

            // c = fl(fl(s1+s2)+s3); dist = fl(fl(a+b) - 2c); strict < = first idx
            const int col0 = ch * CHUNK + nt * 8 + qsub * 2;
            const float b0 = Bn[col0], b1 = Bn[col0 + 1];
            #pragma unroll
            for (int j = 0; j < 4; j++) {
                const int m = j >> 1, h = (j & 1) * 2;
                float c0 = __fadd_rn(__fadd_rn(s1[m][h], s2[m][h]), s3[m][h]);
                float c1 = __fadd_rn(__fadd_rn(s1[m][h+1], s2[m][h+1]), s3[m][h+1]);
                float d0 = __fsub_rn(__fadd_rn(a[j], b0), 2.0f * c0);
                float d1 = __fsub_rn(__fadd_rn(a[j], b1), 2.0f * c1);
                if (d0 < bestD[j]) { bestD[j] = d0; bestI[j] = col0; }
                if (d1 < bestD[j]) { bestD[j] = d1; bestI[j] = col0 + 1; }
            }
        }
        __syncthreads();   // before EsP restaged
    }

    // ---- quad reduce (qsub lanes share rows), first-index tie-break ----
    #pragma unroll
    for (int j = 0; j < 4; j++) {
        float d = bestD[j];
        int   idx = bestI[j];
        #pragma unroll
        for (int off = 1; off <= 2; off <<= 1) {
            float od = __shfl_xor_sync(0xffffffffu, d, off);
            int   oi = __shfl_xor_sync(0xffffffffu, idx, off);
            if (od < d || (od == d && oi < idx)) { d = od; idx = oi; }
        }
        if (qsub == 0)
            IdxS[w * 32 + (j >> 1) * 16 + (j & 1) * 8 + qid] = idx;
    }
    __syncthreads();

    // ---- gather + straight-through write (scalar stores) + fp64 loss ----
    double ls = 0.0;
    {
        const int seg  = tid & 15;
        const int rsub = tid >> 4;
        #pragma unroll
        for (int p = 0; p < 16; p++) {
            int row = p * 8 + rsub;
            int idx = IdxS[row];
            float4 q = __ldg((const float4*)(emb + (size_t)idx * DDIM + seg * 4));
            float4 l = __ldg((const float4*)(lat + (size_t)(rowBase + row) * DDIM + seg * 4));
            float t0 = q.x - l.x, t1 = q.y - l.y, t2 = q.z - l.z, t3 = q.w - l.w;
            ls += (double)t0 * t0 + (double)t1 * t1
                + (double)t2 * t2 + (double)t3 * t3;
            float* o = quant + (size_t)(rowBase + row) * DDIM + seg * 4;
            o[0] = l.x + t0;
            o[1] = l.y + t1;
            o[2] = l.z + t2;
            o[3] = l.w + t3;
        }
    }

    #pragma unroll
    for (int off = 16; off >= 1; off >>= 1)
        ls += __shfl_xor_sync(0xffffffffu, ls, off);
    if (lane == 0) Wsum[w] = ls;
    __syncthreads();
    if (tid == 0)
        g_part[blockIdx.x] = Wsum[0] + Wsum[1] + Wsum[2] + Wsum[3];
}

// ---------------- finalize vq_loss ----------------
__global__ void vq_finalize_kernel(float* __restrict__ out) {
    __shared__ double sm2[NCTAS];
    int t = threadIdx.x;
    sm2[t] = g_part[t];
    __syncthreads();
    for (int s = NCTAS / 2; s >= 1; s >>= 1) {
        if (t < s) sm2[t] += sm2[t + s];
        __syncthreads();
    }
    if (t == 0) {
        double m = sm2[0] / (double)((size_t)NROWS * DDIM);
        out[0] = (float)(1.25 * m);
    }
}

extern "C" void kernel_launch(void* const* d_in, const int* in_sizes, int n_in,
                              void* d_out, int out_size) {
    const float* lat = (const float*)d_in[0];   // latents  [65536, 64]
    const float* emb = (const float*)d_in[1];   // embedding [512, 64]
    float* out = (float*)d_out;

    cudaFuncSetAttribute(vq_mma_kernel, cudaFuncAttributeMaxDynamicSharedMemorySize, SM_TOTAL);
    vq_mma_kernel<<<NCTAS, NTHREADS, SM_TOTAL>>>(lat, emb, out + 1);
    vq_finalize_kernel<<<1, NCTAS>>>(out);
}

// round 8
// speedup vs baseline: 2.0757x; 2.0502x over previous
#include <cuda_runtime.h>
#include <cuda_fp16.h>
#include <math_constants.h>
#include <cstdint>

// VectorQuantizer: emulated-fp32 GEMM via 2-split fp16 mma.sync m16n8k16.
// latents [65536,64] f32, embedding [512,64] f32.
// out[0] = vq_loss, out[1..] = quantized_st (4B-aligned only -> scalar stores).
//
// dist = fl(fl(a+b) - 2c); a,b sequential fp32 chains (exact vs reference grid).
// c: E scaled by 512 (exact pow2; whole fp32 sum scales equivariantly, undone
// by *1/256 for 2c). x = hx+lx, e' = he+le fp16 splits (subtractions exact,
// fp16*fp16 products exact in fp32 accum). 3 passes hi*lo, lo*hi, hi*hi;
// residual (lo*lo + split tails) ~4e-9 on c -- same class as R6/R7 (rel_err 0.0).

#define NROWS 65536
#define KEMB 512
#define DDIM 64
#define TILE_M 128
#define NCTAS (NROWS / TILE_M)   // 512
#define NTHREADS 128             // 4 warps; warp owns 32 rows (2 m16 tiles)
#define NT_TILES (KEMB / 8)      // 64 n-tiles of 8 codes
#define KT 4                     // 4 k-tiles of k16 -> K=64

// device scratch (allowed: no runtime allocation)
__device__ uint4  g_apack[NCTAS * 8 * KT * 2 * 32];  // 16 MB: A frags hi/lo
__device__ uint4  g_epack[KT * KEMB * 4];            // 128 KB: B cells
__device__ float  g_as[NROWS];                       // ||x||^2 exact chains
__device__ float  g_bn[KEMB];                        // ||e||^2 exact chains
__device__ double g_part[NCTAS];

__device__ __forceinline__ uint32_t pack_h2(__half lo, __half hi) {
    return (uint32_t)__half_as_ushort(lo) | ((uint32_t)__half_as_ushort(hi) << 16);
}
__device__ __forceinline__ void split_h(float v, __half& h, __half& l) {
    h = __float2half_rn(v);
    l = __float2half_rn(__fsub_rn(v, __half2float(h)));
}
__device__ __forceinline__ void mma_f16(float* d, const uint4 a,
                                        uint32_t b0, uint32_t b1) {
    asm volatile(
        "mma.sync.aligned.m16n8k16.row.col.f32.f16.f16.f32 "
        "{%0,%1,%2,%3}, {%4,%5,%6,%7}, {%8,%9}, {%0,%1,%2,%3};"
        : "+f"(d[0]), "+f"(d[1]), "+f"(d[2]), "+f"(d[3])
        : "r"(a.x), "r"(a.y), "r"(a.z), "r"(a.w), "r"(b0), "r"(b1));
}

// ---------------- pre-kernel: pack A/E fragments + norms ----------------
// blocks 0..7: E cells + Bn. blocks 8..519: A tile packs + As.
__global__ __launch_bounds__(128)
void vq_pack_kernel(const float* __restrict__ lat, const float* __restrict__ emb) {
    const int tid = threadIdx.x;
    if (blockIdx.x < 8) {
        const int b = blockIdx.x;
        if (tid < 64) {                 // Bn: sequential fp32 chain on RAW e
            int n = b * 64 + tid;
            const float* e = emb + (size_t)n * DDIM;
            float s = 0.f;
            #pragma unroll
            for (int d = 0; d < DDIM; d++)
                s = __fadd_rn(s, __fmul_rn(e[d], e[d]));
            g_bn[n] = s;
        }
        // 1024 cells: (kt, n_loc, qsub)
        #pragma unroll
        for (int s = 0; s < 8; s++) {
            int ci = s * 128 + tid;
            int kt = ci >> 8, rem = ci & 255;
            int nl = rem >> 2, qs = rem & 3;
            int n = b * 64 + nl;
            int k0 = kt * 16 + 2 * qs;
            float2 e01 = __ldg((const float2*)(emb + (size_t)n * DDIM + k0));
            float2 e89 = __ldg((const float2*)(emb + (size_t)n * DDIM + k0 + 8));
            __half h0,l0,h1,l1,h2,l2,h3,l3;
            split_h(512.f * e01.x, h0, l0); split_h(512.f * e01.y, h1, l1);
            split_h(512.f * e89.x, h2, l2); split_h(512.f * e89.y, h3, l3);
            uint4 c;
            c.x = pack_h2(h0, h1);  // b0 hi (k0, k0+1)
            c.y = pack_h2(h2, h3);  // b1 hi (k0+8, k0+9)
            c.z = pack_h2(l0, l1);  // b0 lo
            c.w = pack_h2(l2, l3);  // b1 lo
            g_epack[(kt * KEMB + n) * 4 + qs] = c;
        }
    } else {
        const int tile = blockIdx.x - 8;
        {   // As: sequential fp32 chain
            int row = tile * TILE_M + tid;
            const float* x = lat + (size_t)row * DDIM;
            float s = 0.f;
            #pragma unroll
            for (int d = 0; d < DDIM; d++)
                s = __fadd_rn(s, __fmul_rn(x[d], x[d]));
            g_as[row] = s;
        }
        // 1024 cell-pairs: (g 0..7, kt 0..3, lane 0..31)
        #pragma unroll
        for (int s = 0; s < 8; s++) {
            int ci = s * 128 + tid;
            int g = ci >> 7, kt = (ci >> 5) & 3, lane = ci & 31;
            int qid = lane >> 2, qs = lane & 3;
            int r0 = tile * TILE_M + g * 16 + qid, r1 = r0 + 8;
            int k0 = kt * 16 + 2 * qs;
            float2 x00 = __ldg((const float2*)(lat + (size_t)r0 * DDIM + k0));
            float2 x10 = __ldg((const float2*)(lat + (size_t)r1 * DDIM + k0));
            float2 x02 = __ldg((const float2*)(lat + (size_t)r0 * DDIM + k0 + 8));
            float2 x12 = __ldg((const float2*)(lat + (size_t)r1 * DDIM + k0 + 8));
            __half ah[8], al[8];
            split_h(x00.x, ah[0], al[0]); split_h(x00.y, ah[1], al[1]);
            split_h(x10.x, ah[2], al[2]); split_h(x10.y, ah[3], al[3]);
            split_h(x02.x, ah[4], al[4]); split_h(x02.y, ah[5], al[5]);
            split_h(x12.x, ah[6], al[6]); split_h(x12.y, ah[7], al[7]);
            uint4 hi, lo;
            hi.x = pack_h2(ah[0], ah[1]); hi.y = pack_h2(ah[2], ah[3]);
            hi.z = pack_h2(ah[4], ah[5]); hi.w = pack_h2(ah[6], ah[7]);
            lo.x = pack_h2(al[0], al[1]); lo.y = pack_h2(al[2], al[3]);
            lo.z = pack_h2(al[4], al[5]); lo.w = pack_h2(al[6], al[7]);
            size_t base = ((size_t)(tile * 8 + g) * KT + kt) * 2;
            g_apack[(base + 0) * 32 + lane] = hi;
            g_apack[(base + 1) * 32 + lane] = lo;
        }
    }
}

// ---------------- main kernel ----------------
__global__ __launch_bounds__(NTHREADS, 3)
void vq_mma_kernel(const float* __restrict__ lat,
                   const float* __restrict__ emb,
                   float* __restrict__ quant /* d_out + 1, 4B-aligned only */)
{
    __shared__ float  BnS[KEMB];
    __shared__ int    IdxS[TILE_M];
    __shared__ double Wsum[4];

    const int tid  = threadIdx.x;
    const int w    = tid >> 5;
    const int lane = tid & 31;
    const int qid  = lane >> 2;
    const int qsub = lane & 3;
    const int rowBase = blockIdx.x * TILE_M;

    #pragma unroll
    for (int i = 0; i < 4; i++) BnS[i * NTHREADS + tid] = g_bn[i * NTHREADS + tid];

    // A fragments: [mt][kt] hi/lo
    uint4 AH[2][KT], AL[2][KT];
    #pragma unroll
    for (int mt = 0; mt < 2; mt++)
        #pragma unroll
        for (int kt = 0; kt < KT; kt++) {
            size_t base = ((size_t)(blockIdx.x * 8 + w * 2 + mt) * KT + kt) * 2;
            AH[mt][kt] = __ldg(&g_apack[(base + 0) * 32 + lane]);
            AL[mt][kt] = __ldg(&g_apack[(base + 1) * 32 + lane]);
        }
    float a[4];
    #pragma unroll
    for (int j = 0; j < 4; j++)
        a[j] = __ldg(&g_as[rowBase + w * 32 + (j >> 1) * 16 + (j & 1) * 8 + qid]);
    __syncthreads();

    float bestD[4];
    int   bestI[4];
    #pragma unroll
    for (int j = 0; j < 4; j++) { bestD[j] = CUDART_INF_F; bestI[j] = 0; }

    #pragma unroll 2
    for (int nt = 0; nt < NT_TILES; nt++) {
        uint4 Bc[KT];
        #pragma unroll
        for (int kt = 0; kt < KT; kt++)
            Bc[kt] = __ldg(&g_epack[(kt * KEMB + nt * 8 + qid) * 4 + qsub]);

        float s1[2][4], s2[2][4], s3[2][4];
        #pragma unroll
        for (int m = 0; m < 2; m++)
            #pragma unroll
            for (int q = 0; q < 4; q++) { s1[m][q] = 0.f; s2[m][q] = 0.f; s3[m][q] = 0.f; }

        #pragma unroll
        for (int kt = 0; kt < KT; kt++) {
            mma_f16(s1[0], AH[0][kt], Bc[kt].z, Bc[kt].w);  // hi * lo
            mma_f16(s1[1], AH[1][kt], Bc[kt].z, Bc[kt].w);
            mma_f16(s2[0], AL[0][kt], Bc[kt].x, Bc[kt].y);  // lo * hi
            mma_f16(s2[1], AL[1][kt], Bc[kt].x, Bc[kt].y);
            mma_f16(s3[0], AH[0][kt], Bc[kt].x, Bc[kt].y);  // hi * hi
            mma_f16(s3[1], AH[1][kt], Bc[kt].x, Bc[kt].y);
        }

        // 2c = S/256 (exact pow2 unscale); dist = fl(fl(a+b) - 2c)
        const int col0 = nt * 8 + qsub * 2;
        const float b0 = BnS[col0], b1 = BnS[col0 + 1];
        #pragma unroll
        for (int j = 0; j < 4; j++) {
            const int m = j >> 1, h = (j & 1) * 2;
            float S0 = __fadd_rn(__fadd_rn(s1[m][h],   s2[m][h]),   s3[m][h]);
            float S1 = __fadd_rn(__fadd_rn(s1[m][h+1], s2[m][h+1]), s3[m][h+1]);
            float d0 = __fsub_rn(__fadd_rn(a[j], b0), S0 * 0.00390625f);
            float d1 = __fsub_rn(__fadd_rn(a[j], b1), S1 * 0.00390625f);
            if (d0 < bestD[j]) { bestD[j] = d0; bestI[j] = col0; }
            if (d1 < bestD[j]) { bestD[j] = d1; bestI[j] = col0 + 1; }
        }
    }

    // ---- quad reduce (qsub lanes share rows), first-index tie-break ----
    #pragma unroll
    for (int j = 0; j < 4; j++) {
        float d = bestD[j];
        int   idx = bestI[j];
        #pragma unroll
        for (int off = 1; off <= 2; off <<= 1) {
            float od = __shfl_xor_sync(0xffffffffu, d, off);
            int   oi = __shfl_xor_sync(0xffffffffu, idx, off);
            if (od < d || (od == d && oi < idx)) { d = od; idx = oi; }
        }
        if (qsub == 0)
            IdxS[w * 32 + (j >> 1) * 16 + (j & 1) * 8 + qid] = idx;
    }
    __syncthreads();

    // ---- gather + straight-through write (scalar stores) + fp64 loss ----
    double ls = 0.0;
    {
        const int seg  = tid & 15;
        const int rsub = tid >> 4;
        #pragma unroll
        for (int p = 0; p < 16; p++) {
            int row = p * 8 + rsub;
            int idx = IdxS[row];
            float4 q = __ldg((const float4*)(emb + (size_t)idx * DDIM + seg * 4));
            float4 l = __ldg((const float4*)(lat + (size_t)(rowBase + row) * DDIM + seg * 4));
            float t0 = q.x - l.x, t1 = q.y - l.y, t2 = q.z - l.z, t3 = q.w - l.w;
            ls += (double)t0 * t0 + (double)t1 * t1
                + (double)t2 * t2 + (double)t3 * t3;
            float* o = quant + (size_t)(rowBase + row) * DDIM + seg * 4;
            o[0] = l.x + t0;
            o[1] = l.y + t1;
            o[2] = l.z + t2;
            o[3] = l.w + t3;
        }
    }

    #pragma unroll
    for (int off = 16; off >= 1; off >>= 1)
        ls += __shfl_xor_sync(0xffffffffu, ls, off);
    if (lane == 0) Wsum[w] = ls;
    __syncthreads();
    if (tid == 0)
        g_part[blockIdx.x] = Wsum[0] + Wsum[1] + Wsum[2] + Wsum[3];
}

// ---------------- finalize vq_loss ----------------
__global__ void vq_finalize_kernel(float* __restrict__ out) {
    __shared__ double sm2[NCTAS];
    int t = threadIdx.x;
    sm2[t] = g_part[t];
    __syncthreads();
    for (int s = NCTAS / 2; s >= 1; s >>= 1) {
        if (t < s) sm2[t] += sm2[t + s];
        __syncthreads();
    }
    if (t == 0) {
        double m = sm2[0] / (double)((size_t)NROWS * DDIM);
        out[0] = (float)(1.25 * m);
    }
}

extern "C" void kernel_launch(void* const* d_in, const int* in_sizes, int n_in,
                              void* d_out, int out_size) {
    const float* lat = (const float*)d_in[0];   // latents  [65536, 64]
    const float* emb = (const float*)d_in[1];   // embedding [512, 64]
    float* out = (float*)d_out;

    vq_pack_kernel<<<8 + NCTAS, 128>>>(lat, emb);
    vq_mma_kernel<<<NCTAS, NTHREADS>>>(lat, emb, out + 1);
    vq_finalize_kernel<<<1, NCTAS>>>(out);
}

// round 9
// speedup vs baseline: 2.2060x; 1.0628x over previous
#include <cuda_runtime.h>
#include <cuda_fp16.h>
#include <math_constants.h>
#include <cstdint>

// VectorQuantizer: emulated-fp32 GEMM via 2-split fp16 mma.sync m16n8k16.
// latents [65536,64] f32, embedding [512,64] f32.
// out[0] = vq_loss, out[1..] = quantized_st (4B-aligned only -> scalar stores).
//
// dist = fl(fl(a+b) - 2c); a,b sequential fp32 chains (exact vs reference grid).
// c: E scaled by 512 (exact pow2, undone by *1/256 on 2c); x and e' split into
// fp16 hi+lo (splits exact, fp16*fp16 products exact in fp32 accumulators).
// 3 passes hi*lo, lo*hi, hi*hi; residual ~4e-9 on c (R6/R8: rel_err 0.0).
// R9: A-frag packing + ||x||^2 fused into main (kills 16MB roundtrip kernel),
// finalize fused via last-CTA reduction.

#define NROWS 65536
#define KEMB 512
#define DDIM 64
#define TILE_M 128
#define NCTAS (NROWS / TILE_M)   // 512
#define NTHREADS 128             // 4 warps; warp owns 32 rows (2 m16 tiles)
#define NT_TILES (KEMB / 8)      // 64 n-tiles of 8 codes
#define KT 4                     // 4 k-tiles of k16 -> K=64

__device__ uint4  g_epack[KT * KEMB * 4];  // 128 KB: B cells
__device__ float  g_bn[KEMB];              // ||e||^2 exact chains
__device__ double g_part[NCTAS];
__device__ int    g_cnt = 0;               // last-CTA ticket (self-resetting)

__device__ __forceinline__ uint32_t pack_h2(__half lo, __half hi) {
    return (uint32_t)__half_as_ushort(lo) | ((uint32_t)__half_as_ushort(hi) << 16);
}
__device__ __forceinline__ void split_h(float v, __half& h, __half& l) {
    h = __float2half_rn(v);
    l = __float2half_rn(__fsub_rn(v, __half2float(h)));
}
__device__ __forceinline__ void mma_f16(float* d, const uint4 a,
                                        uint32_t b0, uint32_t b1) {
    asm volatile(
        "mma.sync.aligned.m16n8k16.row.col.f32.f16.f16.f32 "
        "{%0,%1,%2,%3}, {%4,%5,%6,%7}, {%8,%9}, {%0,%1,%2,%3};"
        : "+f"(d[0]), "+f"(d[1]), "+f"(d[2]), "+f"(d[3])
        : "r"(a.x), "r"(a.y), "r"(a.z), "r"(a.w), "r"(b0), "r"(b1));
}

// ---------------- pre-kernel (8 blocks): E cells + ||e||^2 ----------------
__global__ __launch_bounds__(128)
void vq_epack_kernel(const float* __restrict__ emb) {
    const int tid = threadIdx.x;
    const int b = blockIdx.x;
    if (tid < 64) {                 // Bn: sequential fp32 chain on raw e
        int n = b * 64 + tid;
        const float* e = emb + (size_t)n * DDIM;
        float s = 0.f;
        #pragma unroll
        for (int d = 0; d < DDIM; d++)
            s = __fadd_rn(s, __fmul_rn(e[d], e[d]));
        g_bn[n] = s;
    }
    // 1024 cells per block: (kt, n_loc, qsub)
    #pragma unroll
    for (int s = 0; s < 8; s++) {
        int ci = s * 128 + tid;
        int kt = ci >> 8, rem = ci & 255;
        int nl = rem >> 2, qs = rem & 3;
        int n = b * 64 + nl;
        int k0 = kt * 16 + 2 * qs;
        float2 e01 = __ldg((const float2*)(emb + (size_t)n * DDIM + k0));
        float2 e89 = __ldg((const float2*)(emb + (size_t)n * DDIM + k0 + 8));
        __half h0,l0,h1,l1,h2,l2,h3,l3;
        split_h(512.f * e01.x, h0, l0); split_h(512.f * e01.y, h1, l1);
        split_h(512.f * e89.x, h2, l2); split_h(512.f * e89.y, h3, l3);
        uint4 c;
        c.x = pack_h2(h0, h1);  // b0 hi (k0, k0+1)
        c.y = pack_h2(h2, h3);  // b1 hi (k0+8, k0+9)
        c.z = pack_h2(l0, l1);  // b0 lo
        c.w = pack_h2(l2, l3);  // b1 lo
        g_epack[(kt * KEMB + n) * 4 + qs] = c;
    }
}

// ---------------- main kernel ----------------
__global__ __launch_bounds__(NTHREADS, 3)
void vq_mma_kernel(const float* __restrict__ lat,
                   const float* __restrict__ emb,
                   float* __restrict__ out /* d_out; quant = out+1 */)
{
    __shared__ float  BnS[KEMB];
    __shared__ float  AsS[TILE_M];
    __shared__ int    IdxS[TILE_M];
    __shared__ double Wsum[4];
    __shared__ int    lastFlag;

    float* quant = out + 1;

    const int tid  = threadIdx.x;
    const int w    = tid >> 5;
    const int lane = tid & 31;
    const int qid  = lane >> 2;
    const int qsub = lane & 3;
    const int rowBase = blockIdx.x * TILE_M;

    #pragma unroll
    for (int i = 0; i < 4; i++) BnS[i * NTHREADS + tid] = g_bn[i * NTHREADS + tid];

    // ---- a = ||x||^2: sequential fp32 chain (one row per thread) ----
    {
        const float* x = lat + (size_t)(rowBase + tid) * DDIM;
        float s = 0.f;
        #pragma unroll
        for (int d = 0; d < DDIM; d++)
            s = __fadd_rn(s, __fmul_rn(__ldg(x + d), __ldg(x + d)));
        AsS[tid] = s;
    }

    // ---- A fragments: direct LDG + in-register fp16 split ----
    uint4 AH[2][KT], AL[2][KT];
    #pragma unroll
    for (int mt = 0; mt < 2; mt++) {
        const size_t r0 = (size_t)(rowBase + w * 32 + mt * 16 + qid) * DDIM;
        const size_t r1 = r0 + 8 * DDIM;
        #pragma unroll
        for (int kt = 0; kt < KT; kt++) {
            const int k0 = kt * 16 + 2 * qsub;
            float2 x00 = __ldg((const float2*)(lat + r0 + k0));
            float2 x10 = __ldg((const float2*)(lat + r1 + k0));
            float2 x02 = __ldg((const float2*)(lat + r0 + k0 + 8));
            float2 x12 = __ldg((const float2*)(lat + r1 + k0 + 8));
            __half ah[8], al[8];
            split_h(x00.x, ah[0], al[0]); split_h(x00.y, ah[1], al[1]);
            split_h(x10.x, ah[2], al[2]); split_h(x10.y, ah[3], al[3]);
            split_h(x02.x, ah[4], al[4]); split_h(x02.y, ah[5], al[5]);
            split_h(x12.x, ah[6], al[6]); split_h(x12.y, ah[7], al[7]);
            AH[mt][kt] = make_uint4(pack_h2(ah[0], ah[1]), pack_h2(ah[2], ah[3]),
                                    pack_h2(ah[4], ah[5]), pack_h2(ah[6], ah[7]));
            AL[mt][kt] = make_uint4(pack_h2(al[0], al[1]), pack_h2(al[2], al[3]),
                                    pack_h2(al[4], al[5]), pack_h2(al[6], al[7]));
        }
    }
    __syncthreads();

    float a[4];
    #pragma unroll
    for (int j = 0; j < 4; j++)
        a[j] = AsS[w * 32 + (j >> 1) * 16 + (j & 1) * 8 + qid];

    float bestD[4];
    int   bestI[4];
    #pragma unroll
    for (int j = 0; j < 4; j++) { bestD[j] = CUDART_INF_F; bestI[j] = 0; }

    #pragma unroll 2
    for (int nt = 0; nt < NT_TILES; nt++) {
        uint4 Bc[KT];
        #pragma unroll
        for (int kt = 0; kt < KT; kt++)
            Bc[kt] = __ldg(&g_epack[(kt * KEMB + nt * 8 + qid) * 4 + qsub]);

        float s1[2][4], s2[2][4], s3[2][4];
        #pragma unroll
        for (int m = 0; m < 2; m++)
            #pragma unroll
            for (int q = 0; q < 4; q++) { s1[m][q] = 0.f; s2[m][q] = 0.f; s3[m][q] = 0.f; }

        #pragma unroll
        for (int kt = 0; kt < KT; kt++) {
            mma_f16(s1[0], AH[0][kt], Bc[kt].z, Bc[kt].w);  // hi * lo
            mma_f16(s1[1], AH[1][kt], Bc[kt].z, Bc[kt].w);
            mma_f16(s2[0], AL[0][kt], Bc[kt].x, Bc[kt].y);  // lo * hi
            mma_f16(s2[1], AL[1][kt], Bc[kt].x, Bc[kt].y);
            mma_f16(s3[0], AH[0][kt], Bc[kt].x, Bc[kt].y);  // hi * hi
            mma_f16(s3[1], AH[1][kt], Bc[kt].x, Bc[kt].y);
        }

        // 2c = S/256 (exact pow2 unscale); dist = fl(fl(a+b) - 2c)
        const int col0 = nt * 8 + qsub * 2;
        const float b0 = BnS[col0], b1 = BnS[col0 + 1];
        #pragma unroll
        for (int j = 0; j < 4; j++) {
            const int m = j >> 1, h = (j & 1) * 2;
            float S0 = __fadd_rn(__fadd_rn(s1[m][h],   s2[m][h]),   s3[m][h]);
            float S1 = __fadd_rn(__fadd_rn(s1[m][h+1], s2[m][h+1]), s3[m][h+1]);
            float d0 = __fsub_rn(__fadd_rn(a[j], b0), S0 * 0.00390625f);
            float d1 = __fsub_rn(__fadd_rn(a[j], b1), S1 * 0.00390625f);
            if (d0 < bestD[j]) { bestD[j] = d0; bestI[j] = col0; }
            if (d1 < bestD[j]) { bestD[j] = d1; bestI[j] = col0 + 1; }
        }
    }

    // ---- quad reduce (qsub lanes share rows), first-index tie-break ----
    #pragma unroll
    for (int j = 0; j < 4; j++) {
        float d = bestD[j];
        int   idx = bestI[j];
        #pragma unroll
        for (int off = 1; off <= 2; off <<= 1) {
            float od = __shfl_xor_sync(0xffffffffu, d, off);
            int   oi = __shfl_xor_sync(0xffffffffu, idx, off);
            if (od < d || (od == d && oi < idx)) { d = od; idx = oi; }
        }
        if (qsub == 0)
            IdxS[w * 32 + (j >> 1) * 16 + (j & 1) * 8 + qid] = idx;
    }
    __syncthreads();

    // ---- gather + straight-through write (scalar stores) + fp64 loss ----
    double ls = 0.0;
    {
        const int seg  = tid & 15;
        const int rsub = tid >> 4;
        #pragma unroll
        for (int p = 0; p < 16; p++) {
            int row = p * 8 + rsub;
            int idx = IdxS[row];
            float4 q = __ldg((const float4*)(emb + (size_t)idx * DDIM + seg * 4));
            float4 l = __ldg((const float4*)(lat + (size_t)(rowBase + row) * DDIM + seg * 4));
            float t0 = q.x - l.x, t1 = q.y - l.y, t2 = q.z - l.z, t3 = q.w - l.w;
            ls += (double)t0 * t0 + (double)t1 * t1
                + (double)t2 * t2 + (double)t3 * t3;
            float* o = quant + (size_t)(rowBase + row) * DDIM + seg * 4;
            o[0] = l.x + t0;
            o[1] = l.y + t1;
            o[2] = l.z + t2;
            o[3] = l.w + t3;
        }
    }

    #pragma unroll
    for (int off = 16; off >= 1; off >>= 1)
        ls += __shfl_xor_sync(0xffffffffu, ls, off);
    if (lane == 0) Wsum[w] = ls;
    __syncthreads();

    // ---- publish partial, then last CTA reduces (deterministic order) ----
    if (tid == 0) {
        g_part[blockIdx.x] = Wsum[0] + Wsum[1] + Wsum[2] + Wsum[3];
        __threadfence();
        int ticket = atomicAdd(&g_cnt, 1);
        lastFlag = (ticket == NCTAS - 1) ? 1 : 0;
    }
    __syncthreads();
    if (lastFlag) {
        double s = 0.0;
        #pragma unroll
        for (int i = 0; i < NCTAS / NTHREADS; i++)     // fixed order: 4 per thread
            s += g_part[i * NTHREADS + tid];
        #pragma unroll
        for (int off = 16; off >= 1; off >>= 1)
            s += __shfl_xor_sync(0xffffffffu, s, off);
        if (lane == 0) Wsum[w] = s;
        __syncthreads();
        if (tid == 0) {
            double m = (Wsum[0] + Wsum[1] + Wsum[2] + Wsum[3])
                       / (double)((size_t)NROWS * DDIM);
            out[0] = (float)(1.25 * m);
            g_cnt = 0;   // self-reset for graph replay
        }
    }
}

extern "C" void kernel_launch(void* const* d_in, const int* in_sizes, int n_in,
                              void* d_out, int out_size) {
    const float* lat = (const float*)d_in[0];   // latents  [65536, 64]
    const float* emb = (const float*)d_in[1];   // embedding [512, 64]
    float* out = (float*)d_out;

    vq_epack_kernel<<<8, 128>>>(emb);
    vq_mma_kernel<<<NCTAS, NTHREADS>>>(lat, emb, out);
}

// round 11
// speedup vs baseline: 2.2447x; 1.0175x over previous
#include <cuda_runtime.h>
#include <cuda_fp16.h>
#include <math_constants.h>
#include <cstdint>

// VectorQuantizer: emulated-fp32 GEMM via 2-split fp16 mma.sync m16n8k16.
// latents [65536,64] f32, embedding [512,64] f32.
// out[0] = vq_loss, out[1..] = quantized_st (4B-aligned only -> scalar stores).
//
// dist = fl(fl(a+b) - 2c); a,b sequential fp32 chains (exact vs reference grid).
// c: E scaled by 512 (exact pow2, undone by *1/256 on 2c); x,e' split fp16 hi+lo
// (splits exact, products exact in fp32 accum). 3 passes; residual ~4e-9 on c
// (R6/R8/R9: rel_err 0.0 every time).
// R10: warp tile halved to 1 m-tile (TILE_M=64, 1024 CTAs) -> ~100 regs,
// occupancy 5 CTAs/SM (20 warps) vs 3 (12 warps); latency-bound fix.
// (R11 = identical resubmit: R10 bench was an infra failure, theory untested.)

#define NROWS 65536
#define KEMB 512
#define DDIM 64
#define TILE_M 64
#define NCTAS (NROWS / TILE_M)   // 1024
#define NTHREADS 128             // 4 warps; warp owns 16 rows (1 m16 tile)
#define NT_TILES (KEMB / 8)      // 64 n-tiles of 8 codes
#define KT 4                     // 4 k-tiles of k16 -> K=64

__device__ uint4  g_epack[KT * KEMB * 4];  // 128 KB: B cells
__device__ float  g_bn[KEMB];              // ||e||^2 exact chains
__device__ double g_part[NCTAS];
__device__ int    g_cnt = 0;               // last-CTA ticket (self-resetting)

__device__ __forceinline__ uint32_t pack_h2(__half lo, __half hi) {
    return (uint32_t)__half_as_ushort(lo) | ((uint32_t)__half_as_ushort(hi) << 16);
}
__device__ __forceinline__ void split_h(float v, __half& h, __half& l) {
    h = __float2half_rn(v);
    l = __float2half_rn(__fsub_rn(v, __half2float(h)));
}
__device__ __forceinline__ void mma_f16(float* d, const uint4 a,
                                        uint32_t b0, uint32_t b1) {
    asm volatile(
        "mma.sync.aligned.m16n8k16.row.col.f32.f16.f16.f32 "
        "{%0,%1,%2,%3}, {%4,%5,%6,%7}, {%8,%9}, {%0,%1,%2,%3};"
        : "+f"(d[0]), "+f"(d[1]), "+f"(d[2]), "+f"(d[3])
        : "r"(a.x), "r"(a.y), "r"(a.z), "r"(a.w), "r"(b0), "r"(b1));
}

// ---------------- pre-kernel (8 blocks): E cells + ||e||^2 ----------------
__global__ __launch_bounds__(128)
void vq_epack_kernel(const float* __restrict__ emb) {
    const int tid = threadIdx.x;
    const int b = blockIdx.x;
    if (tid < 64) {                 // Bn: sequential fp32 chain on raw e
        int n = b * 64 + tid;
        const float* e = emb + (size_t)n * DDIM;
        float s = 0.f;
        #pragma unroll
        for (int d = 0; d < DDIM; d++)
            s = __fadd_rn(s, __fmul_rn(e[d], e[d]));
        g_bn[n] = s;
    }
    #pragma unroll
    for (int s = 0; s < 8; s++) {
        int ci = s * 128 + tid;
        int kt = ci >> 8, rem = ci & 255;
        int nl = rem >> 2, qs = rem & 3;
        int n = b * 64 + nl;
        int k0 = kt * 16 + 2 * qs;
        float2 e01 = __ldg((const float2*)(emb + (size_t)n * DDIM + k0));
        float2 e89 = __ldg((const float2*)(emb + (size_t)n * DDIM + k0 + 8));
        __half h0,l0,h1,l1,h2,l2,h3,l3;
        split_h(512.f * e01.x, h0, l0); split_h(512.f * e01.y, h1, l1);
        split_h(512.f * e89.x, h2, l2); split_h(512.f * e89.y, h3, l3);
        uint4 c;
        c.x = pack_h2(h0, h1);  // b0 hi
        c.y = pack_h2(h2, h3);  // b1 hi
        c.z = pack_h2(l0, l1);  // b0 lo
        c.w = pack_h2(l2, l3);  // b1 lo
        g_epack[(kt * KEMB + n) * 4 + qs] = c;
    }
}

// ---------------- main kernel ----------------
__global__ __launch_bounds__(NTHREADS, 5)
void vq_mma_kernel(const float* __restrict__ lat,
                   const float* __restrict__ emb,
                   float* __restrict__ out /* d_out; quant = out+1 */)
{
    __shared__ float  BnS[KEMB];
    __shared__ float  AsS[TILE_M];
    __shared__ int    IdxS[TILE_M];
    __shared__ double Wsum[4];
    __shared__ int    lastFlag;

    float* quant = out + 1;

    const int tid  = threadIdx.x;
    const int w    = tid >> 5;
    const int lane = tid & 31;
    const int qid  = lane >> 2;
    const int qsub = lane & 3;
    const int rowBase = blockIdx.x * TILE_M;

    #pragma unroll
    for (int i = 0; i < 4; i++) BnS[i * NTHREADS + tid] = g_bn[i * NTHREADS + tid];

    // ---- a = ||x||^2: sequential fp32 chain (rows 0..63 by threads 0..63) ----
    if (tid < TILE_M) {
        const float* x = lat + (size_t)(rowBase + tid) * DDIM;
        float s = 0.f;
        #pragma unroll
        for (int d = 0; d < DDIM; d++)
            s = __fadd_rn(s, __fmul_rn(__ldg(x + d), __ldg(x + d)));
        AsS[tid] = s;
    }

    // ---- A fragments: direct LDG + in-register fp16 split (1 m-tile) ----
    uint4 AH[KT], AL[KT];
    {
        const size_t r0 = (size_t)(rowBase + w * 16 + qid) * DDIM;
        const size_t r1 = r0 + 8 * DDIM;
        #pragma unroll
        for (int kt = 0; kt < KT; kt++) {
            const int k0 = kt * 16 + 2 * qsub;
            float2 x00 = __ldg((const float2*)(lat + r0 + k0));
            float2 x10 = __ldg((const float2*)(lat + r1 + k0));
            float2 x02 = __ldg((const float2*)(lat + r0 + k0 + 8));
            float2 x12 = __ldg((const float2*)(lat + r1 + k0 + 8));
            __half ah[8], al[8];
            split_h(x00.x, ah[0], al[0]); split_h(x00.y, ah[1], al[1]);
            split_h(x10.x, ah[2], al[2]); split_h(x10.y, ah[3], al[3]);
            split_h(x02.x, ah[4], al[4]); split_h(x02.y, ah[5], al[5]);
            split_h(x12.x, ah[6], al[6]); split_h(x12.y, ah[7], al[7]);
            AH[kt] = make_uint4(pack_h2(ah[0], ah[1]), pack_h2(ah[2], ah[3]),
                                pack_h2(ah[4], ah[5]), pack_h2(ah[6], ah[7]));
            AL[kt] = make_uint4(pack_h2(al[0], al[1]), pack_h2(al[2], al[3]),
                                pack_h2(al[4], al[5]), pack_h2(al[6], al[7]));
        }
    }
    __syncthreads();

    float a[2];
    #pragma unroll
    for (int j = 0; j < 2; j++)
        a[j] = AsS[w * 16 + j * 8 + qid];

    float bestD[2];
    int   bestI[2];
    #pragma unroll
    for (int j = 0; j < 2; j++) { bestD[j] = CUDART_INF_F; bestI[j] = 0; }

    #pragma unroll 2
    for (int nt = 0; nt < NT_TILES; nt++) {
        uint4 Bc[KT];
        #pragma unroll
        for (int kt = 0; kt < KT; kt++)
            Bc[kt] = __ldg(&g_epack[(kt * KEMB + nt * 8 + qid) * 4 + qsub]);

        float s1[4], s2[4], s3[4];
        #pragma unroll
        for (int q = 0; q < 4; q++) { s1[q] = 0.f; s2[q] = 0.f; s3[q] = 0.f; }

        #pragma unroll
        for (int kt = 0; kt < KT; kt++) {
            mma_f16(s1, AH[kt], Bc[kt].z, Bc[kt].w);  // hi * lo
            mma_f16(s2, AL[kt], Bc[kt].x, Bc[kt].y);  // lo * hi
            mma_f16(s3, AH[kt], Bc[kt].x, Bc[kt].y);  // hi * hi
        }

        // 2c = S/256 (exact pow2 unscale); dist = fl(fl(a+b) - 2c)
        const int col0 = nt * 8 + qsub * 2;
        const float b0 = BnS[col0], b1 = BnS[col0 + 1];
        #pragma unroll
        for (int j = 0; j < 2; j++) {
            const int h = j * 2;
            float S0 = __fadd_rn(__fadd_rn(s1[h],   s2[h]),   s3[h]);
            float S1 = __fadd_rn(__fadd_rn(s1[h+1], s2[h+1]), s3[h+1]);
            float d0 = __fsub_rn(__fadd_rn(a[j], b0), S0 * 0.00390625f);
            float d1 = __fsub_rn(__fadd_rn(a[j], b1), S1 * 0.00390625f);
            if (d0 < bestD[j]) { bestD[j] = d0; bestI[j] = col0; }
            if (d1 < bestD[j]) { bestD[j] = d1; bestI[j] = col0 + 1; }
        }
    }

    // ---- quad reduce (qsub lanes share rows), first-index tie-break ----
    #pragma unroll
    for (int j = 0; j < 2; j++) {
        float d = bestD[j];
        int   idx = bestI[j];
        #pragma unroll
        for (int off = 1; off <= 2; off <<= 1) {
            float od = __shfl_xor_sync(0xffffffffu, d, off);
            int   oi = __shfl_xor_sync(0xffffffffu, idx, off);
            if (od < d || (od == d && oi < idx)) { d = od; idx = oi; }
        }
        if (qsub == 0)
            IdxS[w * 16 + j * 8 + qid] = idx;
    }
    __syncthreads();

    // ---- gather + straight-through write (scalar stores) + fp64 loss ----
    double ls = 0.0;
    {
        const int seg  = tid & 15;
        const int rsub = tid >> 4;
        #pragma unroll
        for (int p = 0; p < 8; p++) {
            int row = p * 8 + rsub;
            int idx = IdxS[row];
            float4 q = __ldg((const float4*)(emb + (size_t)idx * DDIM + seg * 4));
            float4 l = __ldg((const float4*)(lat + (size_t)(rowBase + row) * DDIM + seg * 4));
            float t0 = q.x - l.x, t1 = q.y - l.y, t2 = q.z - l.z, t3 = q.w - l.w;
            ls += (double)t0 * t0 + (double)t1 * t1
                + (double)t2 * t2 + (double)t3 * t3;
            float* o = quant + (size_t)(rowBase + row) * DDIM + seg * 4;
            o[0] = l.x + t0;
            o[1] = l.y + t1;
            o[2] = l.z + t2;
            o[3] = l.w + t3;
        }
    }

    #pragma unroll
    for (int off = 16; off >= 1; off >>= 1)
        ls += __shfl_xor_sync(0xffffffffu, ls, off);
    if (lane == 0) Wsum[w] = ls;
    __syncthreads();

    // ---- publish partial, then last CTA reduces (deterministic order) ----
    if (tid == 0) {
        g_part[blockIdx.x] = Wsum[0] + Wsum[1] + Wsum[2] + Wsum[3];
        __threadfence();
        int ticket = atomicAdd(&g_cnt, 1);
        lastFlag = (ticket == NCTAS - 1) ? 1 : 0;
    }
    __syncthreads();
    if (lastFlag) {
        double s = 0.0;
        #pragma unroll
        for (int i = 0; i < NCTAS / NTHREADS; i++)     // fixed order: 8 per thread
            s += g_part[i * NTHREADS + tid];
        #pragma unroll
        for (int off = 16; off >= 1; off >>= 1)
            s += __shfl_xor_sync(0xffffffffu, s, off);
        if (lane == 0) Wsum[w] = s;
        __syncthreads();
        if (tid == 0) {
            double m = (Wsum[0] + Wsum[1] + Wsum[2] + Wsum[3])
                       / (double)((size_t)NROWS * DDIM);
            out[0] = (float)(1.25 * m);
            g_cnt = 0;   // self-reset for graph replay
        }
    }
}

extern "C" void kernel_launch(void* const* d_in, const int* in_sizes, int n_in,
                              void* d_out, int out_size) {
    const float* lat = (const float*)d_in[0];   // latents  [65536, 64]
    const float* emb = (const float*)d_in[1];   // embedding [512, 64]
    float* out = (float*)d_out;

    vq_epack_kernel<<<8, 128>>>(emb);
    vq_mma_kernel<<<NCTAS, NTHREADS>>>(lat, emb, out);
}